// round 9
// baseline (speedup 1.0000x reference)
#include <cuda_runtime.h>

// Model_10582799417658: 127-step LSTM-VAE rollout.
// B=4096, D=64, H=256, GATES=1024, L=64, T=128 (127 scan steps).
//
// Round 8: 1024 threads/CTA retry (round 3 failed at 64-reg cap because of
// LDG-prefetch+STS register pressure; cp.async removed that). Tile 4m x 8j
// (16 ull acc = 32 regs), one warp per batch row in tail phases, occ 50%.

#define B_TOT   4096
#define T_STEPS 127
#define D_IN    64
#define HID     256
#define GATE    1024
#define LAT     64
#define BT      32
#define NTH     1024
#define NCTA    (B_TOT / BT)   // 128
#define MS      36             // padded m-stride (floats)
#define PK      8              // phase-1 panel depth (k)
#define NP1     40             // 320 / 8
#define PK2     32             // phase-2 panel depth
#define NP2     8              // 256 / 32
#define SLOTF   8192           // floats per panel slot (32 KB)

// ---- output layout ----
#define N_STATES ((unsigned long long)B_TOT * T_STEPS * D_IN)
#define N_GENS   ((unsigned long long)B_TOT * T_STEPS)
#define N_TOTS   ((unsigned long long)B_TOT * 128)
#define O_STATES 0ULL
#define O_GENS   (O_STATES + N_STATES)
#define O_ONOFF  (O_GENS + N_GENS)
#define O_TPRE   (O_ONOFF + N_GENS)
#define O_TPOST  (O_TPRE + N_TOTS)

typedef unsigned long long ull;

__device__ float g_wgv[HID];
__device__ float g_wov[HID];
__device__ float g_b2[2];
// k-major transposed weights (filled once):
// g_Wt1[k][r] = (k<64 ? Wih[r][k] : Whh[r][k-64]),  r in [0,1024), k in [0,320)
// g_Wt2[k][r] = (r<64 ? Wmu[r][k] : Wvar[r-64][k]), r in [0,128),  k in [0,256)
__device__ float g_Wt1[320 * 1024];
__device__ float g_Wt2[256 * 128];

__device__ __forceinline__ ull pack2s(float a) {   // splat (a, a)
    ull r;
    asm("mov.b64 %0, {%1,%1};" : "=l"(r) : "r"(__float_as_uint(a)));
    return r;
}
__device__ __forceinline__ void fma2(ull &d, ull a, ull b) {
    asm("fma.rn.f32x2 %0, %1, %2, %0;" : "+l"(d) : "l"(a), "l"(b));
}
__device__ __forceinline__ float2 unpack2(ull v) {
    unsigned int lo, hi;
    asm("mov.b64 {%0,%1}, %2;" : "=r"(lo), "=r"(hi) : "l"(v));
    float2 f; f.x = __uint_as_float(lo); f.y = __uint_as_float(hi);
    return f;
}
__device__ __forceinline__ float sig_f(float x) {
    return 1.0f / (1.0f + __expf(-x));
}
__device__ __forceinline__ float tanh_f(float x) {
    return 1.0f - 2.0f / (__expf(2.0f * x) + 1.0f);
}
__device__ __forceinline__ void cpa16(unsigned int dst, const void* src) {
    asm volatile("cp.async.cg.shared.global [%0], [%1], 16;" :: "r"(dst), "l"(src));
}
__device__ __forceinline__ void cpa_commit() {
    asm volatile("cp.async.commit_group;");
}
__device__ __forceinline__ void cpa_wait1() {
    asm volatile("cp.async.wait_group 1;");
}

// Fold velo/switch heads into rank-1 vectors.
__global__ void prep_kernel(const float* __restrict__ Wgen, const float* __restrict__ bgen,
                            const float* __restrict__ Won,  const float* __restrict__ bon,
                            const float* __restrict__ Wvelo, const float* __restrict__ bvelo,
                            const float* __restrict__ Wsw,  const float* __restrict__ bsw) {
    int k = threadIdx.x;
    float s1 = 0.f, s2 = 0.f;
    #pragma unroll 4
    for (int l = 0; l < LAT; ++l) {
        s1 += Wgen[l] * Wvelo[l * HID + k];
        s2 += Won[l]  * Wsw[l * HID + k];
    }
    g_wgv[k] = s1;
    g_wov[k] = s2;
    if (k == 0) {
        float b1 = bgen[0], b2 = bon[0];
        for (int l = 0; l < LAT; ++l) {
            b1 += Wgen[l] * bvelo[l];
            b2 += Won[l]  * bsw[l];
        }
        g_b2[0] = b1; g_b2[1] = b2;
    }
}

// One-time k-major weight transpose.
__global__ void prep2_kernel(const float* __restrict__ Wih, const float* __restrict__ Whh,
                             const float* __restrict__ Wmu, const float* __restrict__ Wvar) {
    const int stride = gridDim.x * blockDim.x;
    const int idx = blockIdx.x * blockDim.x + threadIdx.x;
    for (int i = idx; i < 320 * 1024; i += stride) {
        int k = i >> 10, r = i & 1023;
        g_Wt1[i] = (k < 64) ? Wih[r * D_IN + k] : Whh[r * HID + (k - 64)];
    }
    for (int i = idx; i < 256 * 128; i += stride) {
        int k = i >> 7, r = i & 127;
        g_Wt2[i] = (r < 64) ? Wmu[r * HID + k] : Wvar[(r - 64) * HID + k];
    }
}

__global__ void __launch_bounds__(NTH, 1)
model_kernel(const float* __restrict__ data, const float* __restrict__ locs,
             const float* __restrict__ bih,  const float* __restrict__ bhh,
             const float* __restrict__ bmu,  const float* __restrict__ bvar,
             const float* __restrict__ Wnext, const float* __restrict__ bnext,
             const float* __restrict__ Wloc, const float* __restrict__ bloc,
             const float* __restrict__ eps,  float* __restrict__ out) {
    extern __shared__ float sm[];
    float* xs     = sm;                  // [64][MS]
    float* hs     = xs     + 2304;       // [256][MS]  in-place h
    float* cs     = hs     + 9216;       // [256][MS]
    float* zs     = cs     + 9216;       // [64][MS]
    float* bsum   = zs     + 2304;       // [1024]
    float* wgv    = bsum   + 1024;       // [256]
    float* wov    = wgv    + 256;        // [256]
    float* bmu_s  = wov    + 256;        // [64]
    float* bvar_s = bmu_s  + 64;         // [64]
    float* bnx_s  = bvar_s + 64;         // [64]
    float* wnT    = bnx_s  + 64;         // [64][64]
    float* abuf   = wnT    + 4096;       // [32]
    float* wbA    = abuf   + 32;         // 3 panel slots of SLOTF floats
    float* mus    = wbA;                 // [64][MS]  (reuse slot0 after 2a)
    float* lvs    = wbA + 2304;          // [64][MS]

    const unsigned int wb_u32 =
        (unsigned int)__cvta_generic_to_shared(wbA);

    const int tid   = threadIdx.x;
    const int bBase = blockIdx.x * BT;
    // phase-1 compute tile: 8 m-tiles of 4 rows x 128 j-pairs (x4 gates)
    const int m0A  = (tid & 7) * 4;
    const int jt2A = (tid >> 3) * 2;     // 0..254
    const int wrp = tid >> 5, lane = tid & 31;
    // phase-2a tile: 16 m-tiles of 2 x 64 row-pairs
    const int m02 = (tid & 15) * 2;
    const int jq2 = (tid >> 4) * 2;      // 0..126

    // ---------------- init ----------------
    for (int i = tid; i < HID * MS; i += NTH) cs[i] = 0.f;
    for (int i = tid; i < D_IN * BT; i += NTH) {
        int k = i / BT, m = i % BT;
        xs[k * MS + m] = data[(size_t)(bBase + m) * (128 * D_IN) + k];
    }
    for (int i = tid; i < HID * BT; i += NTH) {
        int j = i / BT, m = i % BT;
        int b = bBase + m;
        hs[j * MS + m] = locs[b * 2] * Wloc[j * 2] + locs[b * 2 + 1] * Wloc[j * 2 + 1] + bloc[j];
    }
    for (int i = tid; i < GATE; i += NTH) bsum[i] = bih[i] + bhh[i];
    for (int i = tid; i < HID; i += NTH) { wgv[i] = g_wgv[i]; wov[i] = g_wov[i]; }
    for (int i = tid; i < LAT; i += NTH) { bmu_s[i] = bmu[i]; bvar_s[i] = bvar[i]; }
    for (int i = tid; i < D_IN; i += NTH) bnx_s[i] = bnext[i];
    for (int i = tid; i < LAT * D_IN; i += NTH) {   // wnT[l][c] = Wnext[c][l]
        int l = i >> 6, c = i & 63;
        wnT[i] = Wnext[c * LAT + l];
    }
    if (tid < BT) {
        out[O_TPRE  + (size_t)(bBase + tid) * 128] = 0.f;
        out[O_TPOST + (size_t)(bBase + tid) * 128] = 0.f;
    }
    const float bgv = g_b2[0], bov = g_b2[1];
    __syncthreads();

    // panel issue helpers (cp.async, 16B granules)
    auto issue1 = [&](int p, int slot) {
        const float4* src = ((const float4*)g_Wt1) + (size_t)p * 2048 + tid;
        unsigned int dst = wb_u32 + (unsigned int)slot * (SLOTF * 4u) + tid * 16u;
        cpa16(dst,          src);
        cpa16(dst + 16384u, src + 1024);
    };
    auto issue2 = [&](int p, int slot) {
        const float4* src = ((const float4*)g_Wt2) + (size_t)p * 1024 + tid;
        unsigned int dst = wb_u32 + (unsigned int)slot * (SLOTF * 4u) + tid * 16u;
        cpa16(dst, src);
    };

    for (int t = 0; t < T_STEPS; ++t) {
        // prefetch eps for phase 2b (one batch row per warp)
        float ea, eb;
        {
            const float* ep = eps + ((size_t)t * B_TOT + bBase + wrp) * LAT;
            ea = __ldg(ep + lane);
            eb = __ldg(ep + lane + 32);
        }

        // ======== Phase 1: gates = x@Wih^T + h@Whh^T, LSTM update ========
        {
            issue1(0, 0); cpa_commit();
            issue1(1, 1); cpa_commit();

            ull acc[16];
            #pragma unroll
            for (int i = 0; i < 16; ++i) acc[i] = 0ULL;

            for (int p = 0; p < NP1; ++p) {
                cpa_wait1();
                __syncthreads();     // panel p visible; slot (p+2)%3 free
                if (p + 2 < NP1) issue1(p + 2, (p + 2) % 3);
                cpa_commit();
                const float* wc = wbA + (p % 3) * SLOTF;
                const float* Ab = (p < 8) ? (xs + p * PK * MS)
                                          : (hs + (p * PK - 64) * MS);
                #pragma unroll
                for (int kk = 0; kk < PK; ++kk) {
                    float4 a0 = *(const float4*)(Ab + kk * MS + m0A);
                    const float* wr = wc + kk * 1024 + jt2A;
                    ull w0 = *(const ull*)(wr);
                    ull w1 = *(const ull*)(wr + 256);
                    ull w2 = *(const ull*)(wr + 512);
                    ull w3 = *(const ull*)(wr + 768);
                    #pragma unroll
                    for (int m = 0; m < 4; ++m) {
                        ull am = pack2s((&a0.x)[m]);
                        fma2(acc[m * 4 + 0], am, w0);
                        fma2(acc[m * 4 + 1], am, w1);
                        fma2(acc[m * 4 + 2], am, w2);
                        fma2(acc[m * 4 + 3], am, w3);
                    }
                }
            }
            __syncthreads();         // all warps done reading hs/panels

            // epilogue: bias + LSTM nonlinearity, h/c in place (4 m rows)
            const int hj0 = jt2A, hj1 = jt2A + 1;
            const float bi0 = bsum[hj0],       bi1 = bsum[hj1];
            const float bf0 = bsum[256 + hj0], bf1 = bsum[256 + hj1];
            const float bg0 = bsum[512 + hj0], bg1 = bsum[512 + hj1];
            const float bo0 = bsum[768 + hj0], bo1 = bsum[768 + hj1];
            #pragma unroll
            for (int m = 0; m < 4; ++m) {
                const int mm = m0A + m;
                float2 vi = unpack2(acc[m * 4 + 0]);
                float2 vf = unpack2(acc[m * 4 + 1]);
                float2 vg = unpack2(acc[m * 4 + 2]);
                float2 vo = unpack2(acc[m * 4 + 3]);
                {
                    float iv = sig_f(vi.x + bi0), fv = sig_f(vf.x + bf0);
                    float gv = tanh_f(vg.x + bg0), ov = sig_f(vo.x + bo0);
                    float c = fv * cs[hj0 * MS + mm] + iv * gv;
                    cs[hj0 * MS + mm] = c;
                    hs[hj0 * MS + mm] = ov * tanh_f(c);
                }
                {
                    float iv = sig_f(vi.y + bi1), fv = sig_f(vf.y + bf1);
                    float gv = tanh_f(vg.y + bg1), ov = sig_f(vo.y + bo1);
                    float c = fv * cs[hj1 * MS + mm] + iv * gv;
                    cs[hj1 * MS + mm] = c;
                    hs[hj1 * MS + mm] = ov * tanh_f(c);
                }
            }
        }

        // ======== Phase 2a: [mu;logvar] = h @ [Wmu;Wvar]^T ========
        {
            issue2(0, 0); cpa_commit();
            issue2(1, 1); cpa_commit();

            ull acc2[2] = {0ULL, 0ULL};

            for (int p = 0; p < NP2; ++p) {
                cpa_wait1();
                __syncthreads();     // also orders phase-1 hs writes at p=0
                if (p + 2 < NP2) issue2(p + 2, (p + 2) % 3);
                cpa_commit();
                const float* wc = wbA + (p % 3) * SLOTF;
                const int k0 = p * PK2;
                #pragma unroll
                for (int kk = 0; kk < PK2; ++kk) {
                    float2 a = *(const float2*)(hs + (k0 + kk) * MS + m02);
                    ull w = *(const ull*)(wc + kk * 128 + jq2);
                    fma2(acc2[0], pack2s(a.x), w);
                    fma2(acc2[1], pack2s(a.y), w);
                }
            }
            __syncthreads();         // all warps done with panel slots

            // epilogue: row pair (jq2, jq2+1) for 2 m rows -> mus/lvs (slot0)
            if (jq2 < 64) {
                const float b0 = bmu_s[jq2], b1 = bmu_s[jq2 + 1];
                #pragma unroll
                for (int m = 0; m < 2; ++m) {
                    float2 v = unpack2(acc2[m]);
                    mus[jq2 * MS + m02 + m]       = v.x + b0;
                    mus[(jq2 + 1) * MS + m02 + m] = v.y + b1;
                }
            } else {
                const int l0 = jq2 - 64;
                const float b0 = bvar_s[l0], b1 = bvar_s[l0 + 1];
                #pragma unroll
                for (int m = 0; m < 2; ++m) {
                    float2 v = unpack2(acc2[m]);
                    lvs[l0 * MS + m02 + m]       = v.x + b0;
                    lvs[(l0 + 1) * MS + m02 + m] = v.y + b1;
                }
            }
        }
        __syncthreads();

        // ======== Phase 2b: gen/on + reparameterized z (warp per row) ======
        {
            const int m = wrp;
            const int b = bBase + m;
            float gp = 0.f, op = 0.f;
            #pragma unroll
            for (int i2 = 0; i2 < 8; ++i2) {
                int k = lane + 32 * i2;
                float hv = hs[k * MS + m];
                gp = fmaf(hv, wgv[k], gp);
                op = fmaf(hv, wov[k], op);
            }
            #pragma unroll
            for (int s2 = 16; s2 > 0; s2 >>= 1) {
                gp += __shfl_xor_sync(0xffffffffu, gp, s2);
                op += __shfl_xor_sync(0xffffffffu, op, s2);
            }
            if (lane == 0) {
                float gen = fmaxf(gp + bgv, 0.f);
                float on  = (op + bov) > 0.f ? 1.f : 0.f;
                abuf[m] = gen * on;
                out[O_GENS  + (size_t)b * T_STEPS + t] = gen;
                out[O_ONOFF + (size_t)b * T_STEPS + t] = on;
            }
            float mu0 = mus[lane * MS + m],        lv0 = lvs[lane * MS + m];
            float mu1 = mus[(lane + 32) * MS + m], lv1 = lvs[(lane + 32) * MS + m];
            zs[lane * MS + m]        = ea * __expf(0.5f * lv0) + mu0;
            zs[(lane + 32) * MS + m] = eb * __expf(0.5f * lv1) + mu1;
        }
        __syncwarp();

        // ======== Phase 3: delta = z@Wnext^T, state, totals (warp per row) ==
        {
            const int m = wrp;
            const int b = bBase + m;
            float d0 = bnx_s[lane], d1 = bnx_s[lane + 32];
            #pragma unroll 8
            for (int l = 0; l < LAT; ++l) {
                float zl = zs[l * MS + m];
                d0 = fmaf(zl, wnT[l * 64 + lane],      d0);
                d1 = fmaf(zl, wnT[l * 64 + lane + 32], d1);
            }
            float xn0 = (lane == 0) ? 0.f : fmaxf(xs[lane * MS + m] + d0, 0.f);
            float xn1 = fmaxf(xs[(lane + 32) * MS + m] + d1, 0.f);
            float part = xn0 + xn1;
            #pragma unroll
            for (int s2 = 16; s2 > 0; s2 >>= 1)
                part += __shfl_xor_sync(0xffffffffu, part, s2);
            float add = abuf[m];
            float v0 = (lane == 0) ? add : xn0;
            size_t ob = O_STATES + ((size_t)b * T_STEPS + t) * D_IN;
            out[ob + lane]      = v0;
            out[ob + lane + 32] = xn1;
            xs[lane * MS + m]        = v0;
            xs[(lane + 32) * MS + m] = xn1;
            if (lane == 0) {
                out[O_TPRE  + (size_t)b * 128 + t + 1] = part;
                out[O_TPOST + (size_t)b * 128 + t + 1] = part + add;
            }
        }
        __syncthreads();   // xs/hs/cs stable before next step's phase 1
    }
}

extern "C" void kernel_launch(void* const* d_in, const int* in_sizes, int n_in,
                              void* d_out, int out_size) {
    const float* data  = (const float*)d_in[0];
    const float* locs  = (const float*)d_in[1];
    const float* Wih   = (const float*)d_in[2];
    const float* Whh   = (const float*)d_in[3];
    const float* bih   = (const float*)d_in[4];
    const float* bhh   = (const float*)d_in[5];
    const float* Wmu   = (const float*)d_in[6];
    const float* bmu   = (const float*)d_in[7];
    const float* Wvar  = (const float*)d_in[8];
    const float* bvar  = (const float*)d_in[9];
    const float* Wvelo = (const float*)d_in[10];
    const float* bvelo = (const float*)d_in[11];
    const float* Wsw   = (const float*)d_in[12];
    const float* bsw   = (const float*)d_in[13];
    const float* Wgen  = (const float*)d_in[14];
    const float* bgen  = (const float*)d_in[15];
    const float* Won   = (const float*)d_in[16];
    const float* bon   = (const float*)d_in[17];
    const float* Wnext = (const float*)d_in[18];
    const float* bnext = (const float*)d_in[19];
    const float* Wloc  = (const float*)d_in[20];
    const float* bloc  = (const float*)d_in[21];
    const float* eps   = (const float*)d_in[22];
    float* out = (float*)d_out;

    prep_kernel<<<1, 256>>>(Wgen, bgen, Won, bon, Wvelo, bvelo, Wsw, bsw);
    prep2_kernel<<<256, 512>>>(Wih, Whh, Wmu, Wvar);

    // floats: 28896 (states etc.) + 3 * 8192 (panel slots) = 53472
    const size_t smem_bytes = 53472 * sizeof(float);  // 213,888 B
    cudaFuncSetAttribute(model_kernel,
                         cudaFuncAttributeMaxDynamicSharedMemorySize,
                         (int)smem_bytes);
    model_kernel<<<NCTA, NTH, smem_bytes>>>(data, locs, bih, bhh,
                                            bmu, bvar, Wnext, bnext,
                                            Wloc, bloc, eps, out);
}

// round 10
// speedup vs baseline: 1.0654x; 1.0654x over previous
#include <cuda_runtime.h>

// Model_10582799417658: 127-step LSTM-VAE rollout.
// B=4096, D=64, H=256, GATES=1024, L=64, T=128 (127 scan steps).
//
// Round 9: round-7 winner (512 thr, cp.async 3-slot ring) +
//  - unified A buffer [320][MS] (x rows 0-63, h rows 64-319)
//  - c state in registers (16 cells/thread, frees 36 KB SMEM, no c LDS/STS)
//  - PK 8->10 (phase-1 syncs 40->32), PK2 32->64 (phase-2a syncs 8->4)

#define B_TOT   4096
#define T_STEPS 127
#define D_IN    64
#define HID     256
#define GATE    1024
#define LAT     64
#define BT      32
#define NTH     512
#define NCTA    (B_TOT / BT)   // 128
#define MS      36             // padded m-stride (floats)
#define PK      10             // phase-1 panel depth (k)
#define NP1     32             // 320 / 10
#define PK2     64             // phase-2 panel depth
#define NP2     4              // 256 / 64
#define SLOTF   10240          // floats per panel slot (40 KB)

// ---- output layout ----
#define N_STATES ((unsigned long long)B_TOT * T_STEPS * D_IN)
#define N_GENS   ((unsigned long long)B_TOT * T_STEPS)
#define N_TOTS   ((unsigned long long)B_TOT * 128)
#define O_STATES 0ULL
#define O_GENS   (O_STATES + N_STATES)
#define O_ONOFF  (O_GENS + N_GENS)
#define O_TPRE   (O_ONOFF + N_GENS)
#define O_TPOST  (O_TPRE + N_TOTS)

typedef unsigned long long ull;

__device__ float g_wgv[HID];
__device__ float g_wov[HID];
__device__ float g_b2[2];
// k-major transposed weights (filled once):
// g_Wt1[k][r] = (k<64 ? Wih[r][k] : Whh[r][k-64]),  r in [0,1024), k in [0,320)
// g_Wt2[k][r] = (r<64 ? Wmu[r][k] : Wvar[r-64][k]), r in [0,128),  k in [0,256)
__device__ float g_Wt1[320 * 1024];
__device__ float g_Wt2[256 * 128];

__device__ __forceinline__ ull pack2s(float a) {   // splat (a, a)
    ull r;
    asm("mov.b64 %0, {%1,%1};" : "=l"(r) : "r"(__float_as_uint(a)));
    return r;
}
__device__ __forceinline__ void fma2(ull &d, ull a, ull b) {
    asm("fma.rn.f32x2 %0, %1, %2, %0;" : "+l"(d) : "l"(a), "l"(b));
}
__device__ __forceinline__ float2 unpack2(ull v) {
    unsigned int lo, hi;
    asm("mov.b64 {%0,%1}, %2;" : "=r"(lo), "=r"(hi) : "l"(v));
    float2 f; f.x = __uint_as_float(lo); f.y = __uint_as_float(hi);
    return f;
}
__device__ __forceinline__ float sig_f(float x) {
    return 1.0f / (1.0f + __expf(-x));
}
__device__ __forceinline__ float tanh_f(float x) {
    return 1.0f - 2.0f / (__expf(2.0f * x) + 1.0f);
}
__device__ __forceinline__ void cpa16(unsigned int dst, const void* src) {
    asm volatile("cp.async.cg.shared.global [%0], [%1], 16;" :: "r"(dst), "l"(src));
}
__device__ __forceinline__ void cpa_commit() {
    asm volatile("cp.async.commit_group;");
}
__device__ __forceinline__ void cpa_wait1() {
    asm volatile("cp.async.wait_group 1;");
}

// Fold velo/switch heads into rank-1 vectors.
__global__ void prep_kernel(const float* __restrict__ Wgen, const float* __restrict__ bgen,
                            const float* __restrict__ Won,  const float* __restrict__ bon,
                            const float* __restrict__ Wvelo, const float* __restrict__ bvelo,
                            const float* __restrict__ Wsw,  const float* __restrict__ bsw) {
    int k = threadIdx.x;
    float s1 = 0.f, s2 = 0.f;
    #pragma unroll 4
    for (int l = 0; l < LAT; ++l) {
        s1 += Wgen[l] * Wvelo[l * HID + k];
        s2 += Won[l]  * Wsw[l * HID + k];
    }
    g_wgv[k] = s1;
    g_wov[k] = s2;
    if (k == 0) {
        float b1 = bgen[0], b2 = bon[0];
        for (int l = 0; l < LAT; ++l) {
            b1 += Wgen[l] * bvelo[l];
            b2 += Won[l]  * bsw[l];
        }
        g_b2[0] = b1; g_b2[1] = b2;
    }
}

// One-time k-major weight transpose.
__global__ void prep2_kernel(const float* __restrict__ Wih, const float* __restrict__ Whh,
                             const float* __restrict__ Wmu, const float* __restrict__ Wvar) {
    const int stride = gridDim.x * blockDim.x;
    const int idx = blockIdx.x * blockDim.x + threadIdx.x;
    for (int i = idx; i < 320 * 1024; i += stride) {
        int k = i >> 10, r = i & 1023;
        g_Wt1[i] = (k < 64) ? Wih[r * D_IN + k] : Whh[r * HID + (k - 64)];
    }
    for (int i = idx; i < 256 * 128; i += stride) {
        int k = i >> 7, r = i & 127;
        g_Wt2[i] = (r < 64) ? Wmu[r * HID + k] : Wvar[(r - 64) * HID + k];
    }
}

__global__ void __launch_bounds__(NTH, 1)
model_kernel(const float* __restrict__ data, const float* __restrict__ locs,
             const float* __restrict__ bih,  const float* __restrict__ bhh,
             const float* __restrict__ bmu,  const float* __restrict__ bvar,
             const float* __restrict__ Wnext, const float* __restrict__ bnext,
             const float* __restrict__ Wloc, const float* __restrict__ bloc,
             const float* __restrict__ eps,  float* __restrict__ out) {
    extern __shared__ float sm[];
    float* As     = sm;                  // [320][MS]: x rows 0-63, h rows 64-319
    float* zs     = As     + 11520;      // [64][MS]
    float* bsum   = zs     + 2304;       // [1024]
    float* wgv    = bsum   + 1024;       // [256]
    float* wov    = wgv    + 256;        // [256]
    float* bmu_s  = wov    + 256;        // [64]
    float* bvar_s = bmu_s  + 64;         // [64]
    float* bnx_s  = bvar_s + 64;         // [64]
    float* wnT    = bnx_s  + 64;         // [64][64]
    float* abuf   = wnT    + 4096;       // [32]
    float* wbA    = abuf   + 32;         // 3 panel slots of SLOTF floats
    float* hsB    = As + 64 * MS;        // h rows (alias into As)
    float* mus    = wbA;                 // [64][MS]  (reuse slot0 after 2a)
    float* lvs    = wbA + 2304;          // [64][MS]

    const unsigned int wb_u32 =
        (unsigned int)__cvta_generic_to_shared(wbA);

    const int tid   = threadIdx.x;
    const int bBase = blockIdx.x * BT;
    // phase-1 compute tile: 4 m-tiles of 8 rows x 128 j-pairs (x4 gates)
    const int m0A  = (tid & 3) * 8;
    const int jt2A = (tid >> 2) * 2;     // 0..254
    const int wrp = tid >> 5, lane = tid & 31;
    // phase-2a tile: 8 m-tiles of 4 x 64 row-pairs
    const int m08 = (tid & 7) * 4;
    const int jq2 = (tid >> 3) * 2;      // 0..126

    // ---------------- init ----------------
    for (int i = tid; i < D_IN * BT; i += NTH) {
        int k = i / BT, m = i % BT;
        As[k * MS + m] = data[(size_t)(bBase + m) * (128 * D_IN) + k];
    }
    for (int i = tid; i < HID * BT; i += NTH) {
        int j = i / BT, m = i % BT;
        int b = bBase + m;
        hsB[j * MS + m] = locs[b * 2] * Wloc[j * 2] + locs[b * 2 + 1] * Wloc[j * 2 + 1] + bloc[j];
    }
    for (int i = tid; i < GATE; i += NTH) bsum[i] = bih[i] + bhh[i];
    for (int i = tid; i < HID; i += NTH) { wgv[i] = g_wgv[i]; wov[i] = g_wov[i]; }
    for (int i = tid; i < LAT; i += NTH) { bmu_s[i] = bmu[i]; bvar_s[i] = bvar[i]; }
    for (int i = tid; i < D_IN; i += NTH) bnx_s[i] = bnext[i];
    for (int i = tid; i < LAT * D_IN; i += NTH) {   // wnT[l][c] = Wnext[c][l]
        int l = i >> 6, c = i & 63;
        wnT[i] = Wnext[c * LAT + l];
    }
    if (tid < BT) {
        out[O_TPRE  + (size_t)(bBase + tid) * 128] = 0.f;
        out[O_TPOST + (size_t)(bBase + tid) * 128] = 0.f;
    }
    const float bgv = g_b2[0], bov = g_b2[1];

    // c state lives in registers: thread owns cols (jt2A, jt2A+1) x rows m0A..m0A+7
    float c_reg[16];
    #pragma unroll
    for (int i = 0; i < 16; ++i) c_reg[i] = 0.f;
    __syncthreads();

    // panel issue helpers (cp.async, 16B granules)
    auto issue1 = [&](int p, int slot) {   // 10240 floats = 5 x 512 float4
        const float4* src = ((const float4*)g_Wt1) + (size_t)p * 2560 + tid;
        unsigned int dst = wb_u32 + (unsigned int)slot * (SLOTF * 4u) + tid * 16u;
        cpa16(dst,          src);
        cpa16(dst + 8192u,  src + 512);
        cpa16(dst + 16384u, src + 1024);
        cpa16(dst + 24576u, src + 1536);
        cpa16(dst + 32768u, src + 2048);
    };
    auto issue2 = [&](int p, int slot) {   // 8192 floats = 4 x 512 float4
        const float4* src = ((const float4*)g_Wt2) + (size_t)p * 2048 + tid;
        unsigned int dst = wb_u32 + (unsigned int)slot * (SLOTF * 4u) + tid * 16u;
        cpa16(dst,          src);
        cpa16(dst + 8192u,  src + 512);
        cpa16(dst + 16384u, src + 1024);
        cpa16(dst + 24576u, src + 1536);
    };

    for (int t = 0; t < T_STEPS; ++t) {
        // prefetch eps for phase 2b
        float ea[2], eb[2];
        {
            const int mr = wrp * 2;
            const float* ep = eps + ((size_t)t * B_TOT + bBase + mr) * LAT;
            ea[0] = __ldg(ep + lane);        eb[0] = __ldg(ep + lane + 32);
            ea[1] = __ldg(ep + LAT + lane);  eb[1] = __ldg(ep + LAT + lane + 32);
        }

        // ======== Phase 1: gates = [x;h]@Wt1, LSTM update ========
        {
            issue1(0, 0); cpa_commit();
            issue1(1, 1); cpa_commit();

            ull acc[32];
            #pragma unroll
            for (int i = 0; i < 32; ++i) acc[i] = 0ULL;

            for (int p = 0; p < NP1; ++p) {
                cpa_wait1();
                __syncthreads();     // panel p visible; slot (p+2)%3 free
                if (p + 2 < NP1) issue1(p + 2, (p + 2) % 3);
                cpa_commit();
                const float* wc = wbA + (p % 3) * SLOTF;
                const float* Ab = As + p * PK * MS;   // unified A: no branch
                #pragma unroll
                for (int kk = 0; kk < PK; ++kk) {
                    float4 a0 = *(const float4*)(Ab + kk * MS + m0A);
                    float4 a1 = *(const float4*)(Ab + kk * MS + m0A + 4);
                    const float* wr = wc + kk * 1024 + jt2A;
                    ull w0 = *(const ull*)(wr);
                    ull w1 = *(const ull*)(wr + 256);
                    ull w2 = *(const ull*)(wr + 512);
                    ull w3 = *(const ull*)(wr + 768);
                    #pragma unroll
                    for (int m = 0; m < 4; ++m) {
                        ull am = pack2s((&a0.x)[m]);
                        fma2(acc[m * 4 + 0], am, w0);
                        fma2(acc[m * 4 + 1], am, w1);
                        fma2(acc[m * 4 + 2], am, w2);
                        fma2(acc[m * 4 + 3], am, w3);
                    }
                    #pragma unroll
                    for (int m = 0; m < 4; ++m) {
                        ull am = pack2s((&a1.x)[m]);
                        fma2(acc[(m + 4) * 4 + 0], am, w0);
                        fma2(acc[(m + 4) * 4 + 1], am, w1);
                        fma2(acc[(m + 4) * 4 + 2], am, w2);
                        fma2(acc[(m + 4) * 4 + 3], am, w3);
                    }
                }
            }
            __syncthreads();         // all warps done reading h/panels

            // epilogue: bias + LSTM nonlinearity; c in regs, h in place
            const int hj0 = jt2A, hj1 = jt2A + 1;
            const float bi0 = bsum[hj0],       bi1 = bsum[hj1];
            const float bf0 = bsum[256 + hj0], bf1 = bsum[256 + hj1];
            const float bg0 = bsum[512 + hj0], bg1 = bsum[512 + hj1];
            const float bo0 = bsum[768 + hj0], bo1 = bsum[768 + hj1];
            #pragma unroll
            for (int m = 0; m < 8; ++m) {
                const int mm = m0A + m;
                float2 vi = unpack2(acc[m * 4 + 0]);
                float2 vf = unpack2(acc[m * 4 + 1]);
                float2 vg = unpack2(acc[m * 4 + 2]);
                float2 vo = unpack2(acc[m * 4 + 3]);
                {
                    float iv = sig_f(vi.x + bi0), fv = sig_f(vf.x + bf0);
                    float gv = tanh_f(vg.x + bg0), ov = sig_f(vo.x + bo0);
                    float c = fv * c_reg[m * 2 + 0] + iv * gv;
                    c_reg[m * 2 + 0] = c;
                    hsB[hj0 * MS + mm] = ov * tanh_f(c);
                }
                {
                    float iv = sig_f(vi.y + bi1), fv = sig_f(vf.y + bf1);
                    float gv = tanh_f(vg.y + bg1), ov = sig_f(vo.y + bo1);
                    float c = fv * c_reg[m * 2 + 1] + iv * gv;
                    c_reg[m * 2 + 1] = c;
                    hsB[hj1 * MS + mm] = ov * tanh_f(c);
                }
            }
        }

        // ======== Phase 2a: [mu;logvar] = h @ [Wmu;Wvar]^T ========
        {
            issue2(0, 0); cpa_commit();
            issue2(1, 1); cpa_commit();

            ull acc2[4] = {0ULL, 0ULL, 0ULL, 0ULL};

            for (int p = 0; p < NP2; ++p) {
                cpa_wait1();
                __syncthreads();     // also orders phase-1 h writes at p=0
                if (p + 2 < NP2) issue2(p + 2, (p + 2) % 3);
                cpa_commit();
                const float* wc = wbA + (p % 3) * SLOTF;
                const int k0 = p * PK2;
                #pragma unroll 16
                for (int kk = 0; kk < PK2; ++kk) {
                    float4 a = *(const float4*)(hsB + (k0 + kk) * MS + m08);
                    ull w = *(const ull*)(wc + kk * 128 + jq2);
                    fma2(acc2[0], pack2s(a.x), w);
                    fma2(acc2[1], pack2s(a.y), w);
                    fma2(acc2[2], pack2s(a.z), w);
                    fma2(acc2[3], pack2s(a.w), w);
                }
            }
            __syncthreads();         // all warps done with panel slots

            // epilogue: row pair (jq2, jq2+1) for 4 m rows -> mus/lvs (slot0)
            if (jq2 < 64) {
                const float b0 = bmu_s[jq2], b1 = bmu_s[jq2 + 1];
                #pragma unroll
                for (int m = 0; m < 4; ++m) {
                    float2 v = unpack2(acc2[m]);
                    mus[jq2 * MS + m08 + m]       = v.x + b0;
                    mus[(jq2 + 1) * MS + m08 + m] = v.y + b1;
                }
            } else {
                const int l0 = jq2 - 64;
                const float b0 = bvar_s[l0], b1 = bvar_s[l0 + 1];
                #pragma unroll
                for (int m = 0; m < 4; ++m) {
                    float2 v = unpack2(acc2[m]);
                    lvs[l0 * MS + m08 + m]       = v.x + b0;
                    lvs[(l0 + 1) * MS + m08 + m] = v.y + b1;
                }
            }
        }
        __syncthreads();

        // ======== Phase 2b: gen/on + reparameterized z ========
        #pragma unroll
        for (int r = 0; r < 2; ++r) {
            const int m = wrp * 2 + r;
            const int b = bBase + m;
            float gp = 0.f, op = 0.f;
            #pragma unroll
            for (int i2 = 0; i2 < 8; ++i2) {
                int k = lane + 32 * i2;
                float hv = hsB[k * MS + m];
                gp = fmaf(hv, wgv[k], gp);
                op = fmaf(hv, wov[k], op);
            }
            #pragma unroll
            for (int s2 = 16; s2 > 0; s2 >>= 1) {
                gp += __shfl_xor_sync(0xffffffffu, gp, s2);
                op += __shfl_xor_sync(0xffffffffu, op, s2);
            }
            if (lane == 0) {
                float gen = fmaxf(gp + bgv, 0.f);
                float on  = (op + bov) > 0.f ? 1.f : 0.f;
                abuf[m] = gen * on;
                out[O_GENS  + (size_t)b * T_STEPS + t] = gen;
                out[O_ONOFF + (size_t)b * T_STEPS + t] = on;
            }
            float mu0 = mus[lane * MS + m],        lv0 = lvs[lane * MS + m];
            float mu1 = mus[(lane + 32) * MS + m], lv1 = lvs[(lane + 32) * MS + m];
            zs[lane * MS + m]        = ea[r] * __expf(0.5f * lv0) + mu0;
            zs[(lane + 32) * MS + m] = eb[r] * __expf(0.5f * lv1) + mu1;
        }
        __syncwarp();

        // ======== Phase 3: delta = z@Wnext^T, state update, totals ========
        #pragma unroll
        for (int r = 0; r < 2; ++r) {
            const int m = wrp * 2 + r;
            const int b = bBase + m;
            float d0 = bnx_s[lane], d1 = bnx_s[lane + 32];
            #pragma unroll 8
            for (int l = 0; l < LAT; ++l) {
                float zl = zs[l * MS + m];
                d0 = fmaf(zl, wnT[l * 64 + lane],      d0);
                d1 = fmaf(zl, wnT[l * 64 + lane + 32], d1);
            }
            float xn0 = (lane == 0) ? 0.f : fmaxf(As[lane * MS + m] + d0, 0.f);
            float xn1 = fmaxf(As[(lane + 32) * MS + m] + d1, 0.f);
            float part = xn0 + xn1;
            #pragma unroll
            for (int s2 = 16; s2 > 0; s2 >>= 1)
                part += __shfl_xor_sync(0xffffffffu, part, s2);
            float add = abuf[m];
            float v0 = (lane == 0) ? add : xn0;
            size_t ob = O_STATES + ((size_t)b * T_STEPS + t) * D_IN;
            out[ob + lane]      = v0;
            out[ob + lane + 32] = xn1;
            As[lane * MS + m]        = v0;
            As[(lane + 32) * MS + m] = xn1;
            if (lane == 0) {
                out[O_TPRE  + (size_t)b * 128 + t + 1] = part;
                out[O_TPOST + (size_t)b * 128 + t + 1] = part + add;
            }
        }
        __syncthreads();   // x/h stable before next step's phase 1
    }
}

extern "C" void kernel_launch(void* const* d_in, const int* in_sizes, int n_in,
                              void* d_out, int out_size) {
    const float* data  = (const float*)d_in[0];
    const float* locs  = (const float*)d_in[1];
    const float* Wih   = (const float*)d_in[2];
    const float* Whh   = (const float*)d_in[3];
    const float* bih   = (const float*)d_in[4];
    const float* bhh   = (const float*)d_in[5];
    const float* Wmu   = (const float*)d_in[6];
    const float* bmu   = (const float*)d_in[7];
    const float* Wvar  = (const float*)d_in[8];
    const float* bvar  = (const float*)d_in[9];
    const float* Wvelo = (const float*)d_in[10];
    const float* bvelo = (const float*)d_in[11];
    const float* Wsw   = (const float*)d_in[12];
    const float* bsw   = (const float*)d_in[13];
    const float* Wgen  = (const float*)d_in[14];
    const float* bgen  = (const float*)d_in[15];
    const float* Won   = (const float*)d_in[16];
    const float* bon   = (const float*)d_in[17];
    const float* Wnext = (const float*)d_in[18];
    const float* bnext = (const float*)d_in[19];
    const float* Wloc  = (const float*)d_in[20];
    const float* bloc  = (const float*)d_in[21];
    const float* eps   = (const float*)d_in[22];
    float* out = (float*)d_out;

    prep_kernel<<<1, 256>>>(Wgen, bgen, Won, bon, Wvelo, bvelo, Wsw, bsw);
    prep2_kernel<<<256, 512>>>(Wih, Whh, Wmu, Wvar);

    // floats: 19680 (state) + 3 * 10240 (panel slots) = 50400
    const size_t smem_bytes = 50400 * sizeof(float);  // 201,600 B
    cudaFuncSetAttribute(model_kernel,
                         cudaFuncAttributeMaxDynamicSharedMemorySize,
                         (int)smem_bytes);
    model_kernel<<<NCTA, NTH, smem_bytes>>>(data, locs, bih, bhh,
                                            bmu, bvar, Wnext, bnext,
                                            Wloc, bloc, eps, out);
}

// round 11
// speedup vs baseline: 1.0943x; 1.0271x over previous
#include <cuda_runtime.h>

// Model_10582799417658: 127-step LSTM-VAE rollout.
// B=4096, D=64, H=256, GATES=1024, L=64, T=128 (127 scan steps).
//
// Round 11 (base = round-7 9553us winner, 512 thr, PK=8/NP1=40, PK2=32/NP2=8):
//  - 4-slot cp.async ring, wait_group 2 (2 panels in flight -> waits hidden)
//  - c state in registers (frees 36 KB SMEM, kills 48 smem ops/thread/step)
//  - gate-interleaved Wt1 layout -> weight LDS = 2x conflict-free LDS.128
//  - prep kernels merged (2 launches per call -> ncu -s5 hits model_kernel)

#define B_TOT   4096
#define T_STEPS 127
#define D_IN    64
#define HID     256
#define GATE    1024
#define LAT     64
#define BT      32
#define NTH     512
#define NCTA    (B_TOT / BT)   // 128
#define MS      36             // padded m-stride (floats)
#define PK      8              // phase-1 panel depth (k)
#define NP1     40             // 320 / 8
#define PK2     32             // phase-2 panel depth
#define NP2     8              // 256 / 32
#define SLOT1   8192           // phase-1 slot stride (floats)
#define SLOT2   4096           // phase-2 slot stride (floats)

// ---- output layout ----
#define N_STATES ((unsigned long long)B_TOT * T_STEPS * D_IN)
#define N_GENS   ((unsigned long long)B_TOT * T_STEPS)
#define N_TOTS   ((unsigned long long)B_TOT * 128)
#define O_STATES 0ULL
#define O_GENS   (O_STATES + N_STATES)
#define O_ONOFF  (O_GENS + N_GENS)
#define O_TPRE   (O_ONOFF + N_GENS)
#define O_TPOST  (O_TPRE + N_TOTS)

typedef unsigned long long ull;

__device__ float g_wgv[HID];
__device__ float g_wov[HID];
__device__ float g_b2[2];
// Phase-1 weights, k-major + gate-interleaved:
//   g_Wt1[k*1024 +       jp*4 + g*2 + jj] = Wg[(g  )*256 + jp*2 + jj][k], g in {0,1}
//   g_Wt1[k*1024 + 512 + jp*4 + g*2 + jj] = Wg[(g+2)*256 + jp*2 + jj][k], g in {0,1}
// where Wg row r: k<64 -> Wih[r][k], else Whh[r][k-64].
// Phase-2: g_Wt2[k][r] = (r<64 ? Wmu[r][k] : Wvar[r-64][k])
__device__ float g_Wt1[320 * 1024];
__device__ float g_Wt2[256 * 128];

__device__ __forceinline__ ull pack2s(float a) {   // splat (a, a)
    ull r;
    asm("mov.b64 %0, {%1,%1};" : "=l"(r) : "r"(__float_as_uint(a)));
    return r;
}
__device__ __forceinline__ void fma2(ull &d, ull a, ull b) {
    asm("fma.rn.f32x2 %0, %1, %2, %0;" : "+l"(d) : "l"(a), "l"(b));
}
__device__ __forceinline__ float2 unpack2(ull v) {
    unsigned int lo, hi;
    asm("mov.b64 {%0,%1}, %2;" : "=r"(lo), "=r"(hi) : "l"(v));
    float2 f; f.x = __uint_as_float(lo); f.y = __uint_as_float(hi);
    return f;
}
__device__ __forceinline__ float sig_f(float x) {
    return 1.0f / (1.0f + __expf(-x));
}
__device__ __forceinline__ float tanh_f(float x) {
    return 1.0f - 2.0f / (__expf(2.0f * x) + 1.0f);
}
__device__ __forceinline__ void cpa16(unsigned int dst, const void* src) {
    asm volatile("cp.async.cg.shared.global [%0], [%1], 16;" :: "r"(dst), "l"(src));
}
__device__ __forceinline__ void cpa_commit() {
    asm volatile("cp.async.commit_group;");
}
__device__ __forceinline__ void cpa_wait2() {
    asm volatile("cp.async.wait_group 2;");
}

// Merged one-time prep: rank-1 head folds + k-major weight transposes.
__global__ void prep_all_kernel(const float* __restrict__ Wih, const float* __restrict__ Whh,
                                const float* __restrict__ Wmu, const float* __restrict__ Wvar,
                                const float* __restrict__ Wgen, const float* __restrict__ bgen,
                                const float* __restrict__ Won,  const float* __restrict__ bon,
                                const float* __restrict__ Wvelo, const float* __restrict__ bvelo,
                                const float* __restrict__ Wsw,  const float* __restrict__ bsw) {
    const int stride = gridDim.x * blockDim.x;
    const int idx = blockIdx.x * blockDim.x + threadIdx.x;

    if (blockIdx.x == 0 && threadIdx.x < HID) {
        int k = threadIdx.x;
        float s1 = 0.f, s2 = 0.f;
        #pragma unroll 4
        for (int l = 0; l < LAT; ++l) {
            s1 += Wgen[l] * Wvelo[l * HID + k];
            s2 += Won[l]  * Wsw[l * HID + k];
        }
        g_wgv[k] = s1;
        g_wov[k] = s2;
        if (k == 0) {
            float b1 = bgen[0], b2 = bon[0];
            for (int l = 0; l < LAT; ++l) {
                b1 += Wgen[l] * bvelo[l];
                b2 += Won[l]  * bsw[l];
            }
            g_b2[0] = b1; g_b2[1] = b2;
        }
    }

    for (int i = idx; i < 320 * 1024; i += stride) {
        int k = i >> 10, d = i & 1023;
        int half = d >> 9, dd = d & 511;
        int jp = dd >> 2, q = dd & 3;
        int g = half * 2 + (q >> 1), jj = q & 1;
        int grow = g * 256 + jp * 2 + jj;
        g_Wt1[i] = (k < 64) ? Wih[grow * D_IN + k] : Whh[grow * HID + (k - 64)];
    }
    for (int i = idx; i < 256 * 128; i += stride) {
        int k = i >> 7, r = i & 127;
        g_Wt2[i] = (r < 64) ? Wmu[r * HID + k] : Wvar[(r - 64) * HID + k];
    }
}

__global__ void __launch_bounds__(NTH, 1)
model_kernel(const float* __restrict__ data, const float* __restrict__ locs,
             const float* __restrict__ bih,  const float* __restrict__ bhh,
             const float* __restrict__ bmu,  const float* __restrict__ bvar,
             const float* __restrict__ Wnext, const float* __restrict__ bnext,
             const float* __restrict__ Wloc, const float* __restrict__ bloc,
             const float* __restrict__ eps,  float* __restrict__ out) {
    extern __shared__ float sm[];
    float* xs     = sm;                  // [64][MS]
    float* hs     = xs     + 2304;       // [256][MS]  in-place h
    float* zs     = hs     + 9216;       // [64][MS]
    float* bsum   = zs     + 2304;       // [1024]
    float* wgv    = bsum   + 1024;       // [256]
    float* wov    = wgv    + 256;        // [256]
    float* bmu_s  = wov    + 256;        // [64]
    float* bvar_s = bmu_s  + 64;         // [64]
    float* bnx_s  = bvar_s + 64;         // [64]
    float* wnT    = bnx_s  + 64;         // [64][64]
    float* abuf   = wnT    + 4096;       // [32]
    float* wbA    = abuf   + 32;         // 4 panel slots (phase1: 8192, phase2: 4096 stride)
    float* mus    = wbA;                 // [64][MS]  (reuse after phase 2a)
    float* lvs    = wbA + 2304;          // [64][MS]

    const unsigned int wb_u32 =
        (unsigned int)__cvta_generic_to_shared(wbA);

    const int tid   = threadIdx.x;
    const int bBase = blockIdx.x * BT;
    // phase-1 tile: 4 m-tiles of 8 rows x 128 j-pairs (x4 gates)
    const int m0A  = (tid & 3) * 8;
    const int jp   = tid >> 2;           // 0..127
    const int jt2A = jp * 2;
    const int wrp = tid >> 5, lane = tid & 31;
    // phase-2a tile: 8 m-tiles of 4 x 64 row-pairs
    const int m08 = (tid & 7) * 4;
    const int jq2 = (tid >> 3) * 2;      // 0..126

    // ---------------- init ----------------
    for (int i = tid; i < D_IN * BT; i += NTH) {
        int k = i / BT, m = i % BT;
        xs[k * MS + m] = data[(size_t)(bBase + m) * (128 * D_IN) + k];
    }
    for (int i = tid; i < HID * BT; i += NTH) {
        int j = i / BT, m = i % BT;
        int b = bBase + m;
        hs[j * MS + m] = locs[b * 2] * Wloc[j * 2] + locs[b * 2 + 1] * Wloc[j * 2 + 1] + bloc[j];
    }
    for (int i = tid; i < GATE; i += NTH) bsum[i] = bih[i] + bhh[i];
    for (int i = tid; i < HID; i += NTH) { wgv[i] = g_wgv[i]; wov[i] = g_wov[i]; }
    for (int i = tid; i < LAT; i += NTH) { bmu_s[i] = bmu[i]; bvar_s[i] = bvar[i]; }
    for (int i = tid; i < D_IN; i += NTH) bnx_s[i] = bnext[i];
    for (int i = tid; i < LAT * D_IN; i += NTH) {   // wnT[l][c] = Wnext[c][l]
        int l = i >> 6, c = i & 63;
        wnT[i] = Wnext[c * LAT + l];
    }
    if (tid < BT) {
        out[O_TPRE  + (size_t)(bBase + tid) * 128] = 0.f;
        out[O_TPOST + (size_t)(bBase + tid) * 128] = 0.f;
    }
    const float bgv = g_b2[0], bov = g_b2[1];

    // c state in registers: this thread owns cols (jt2A, jt2A+1) x rows m0A..m0A+7
    float c_reg[16];
    #pragma unroll
    for (int i = 0; i < 16; ++i) c_reg[i] = 0.f;
    __syncthreads();

    // panel issue helpers (cp.async, 16B granules)
    auto issue1 = [&](int p, int slot) {   // 8192 floats = 4 x 512 float4
        const float4* src = ((const float4*)g_Wt1) + (size_t)p * 2048 + tid;
        unsigned int dst = wb_u32 + (unsigned int)slot * (SLOT1 * 4u) + tid * 16u;
        cpa16(dst,          src);
        cpa16(dst + 8192u,  src + 512);
        cpa16(dst + 16384u, src + 1024);
        cpa16(dst + 24576u, src + 1536);
    };
    auto issue2 = [&](int p, int slot) {   // 4096 floats = 2 x 512 float4
        const float4* src = ((const float4*)g_Wt2) + (size_t)p * 1024 + tid;
        unsigned int dst = wb_u32 + (unsigned int)slot * (SLOT2 * 4u) + tid * 16u;
        cpa16(dst,         src);
        cpa16(dst + 8192u, src + 512);
    };

    for (int t = 0; t < T_STEPS; ++t) {
        // prefetch eps for phase 2b
        float ea[2], eb[2];
        {
            const int mr = wrp * 2;
            const float* ep = eps + ((size_t)t * B_TOT + bBase + mr) * LAT;
            ea[0] = __ldg(ep + lane);        eb[0] = __ldg(ep + lane + 32);
            ea[1] = __ldg(ep + LAT + lane);  eb[1] = __ldg(ep + LAT + lane + 32);
        }

        // ======== Phase 1: gates = x@Wih^T + h@Whh^T, LSTM update ========
        {
            issue1(0, 0); cpa_commit();
            issue1(1, 1); cpa_commit();
            issue1(2, 2); cpa_commit();

            ull acc[32];
            #pragma unroll
            for (int i = 0; i < 32; ++i) acc[i] = 0ULL;

            for (int p = 0; p < NP1; ++p) {
                cpa_wait2();
                __syncthreads();     // panel p visible; slot (p+3)&3 free
                if (p + 3 < NP1) issue1(p + 3, (p + 3) & 3);
                cpa_commit();
                const float* wc = wbA + (p & 3) * SLOT1;
                const float* Ab = (p < 8) ? (xs + p * PK * MS)
                                          : (hs + (p * PK - 64) * MS);
                #pragma unroll
                for (int kk = 0; kk < PK; ++kk) {
                    float4 a0 = *(const float4*)(Ab + kk * MS + m0A);
                    float4 a1 = *(const float4*)(Ab + kk * MS + m0A + 4);
                    const float* wr = wc + kk * 1024 + jp * 4;
                    ulonglong2 wA = *(const ulonglong2*)(wr);        // g0, g1
                    ulonglong2 wB = *(const ulonglong2*)(wr + 512);  // g2, g3
                    ull w0 = wA.x, w1 = wA.y, w2 = wB.x, w3 = wB.y;
                    #pragma unroll
                    for (int m = 0; m < 4; ++m) {
                        ull am = pack2s((&a0.x)[m]);
                        fma2(acc[m * 4 + 0], am, w0);
                        fma2(acc[m * 4 + 1], am, w1);
                        fma2(acc[m * 4 + 2], am, w2);
                        fma2(acc[m * 4 + 3], am, w3);
                    }
                    #pragma unroll
                    for (int m = 0; m < 4; ++m) {
                        ull am = pack2s((&a1.x)[m]);
                        fma2(acc[(m + 4) * 4 + 0], am, w0);
                        fma2(acc[(m + 4) * 4 + 1], am, w1);
                        fma2(acc[(m + 4) * 4 + 2], am, w2);
                        fma2(acc[(m + 4) * 4 + 3], am, w3);
                    }
                }
            }
            __syncthreads();         // all warps done reading hs/panels

            // epilogue: bias + LSTM nonlinearity; c in regs, h in place
            const int hj0 = jt2A, hj1 = jt2A + 1;
            const float bi0 = bsum[hj0],       bi1 = bsum[hj1];
            const float bf0 = bsum[256 + hj0], bf1 = bsum[256 + hj1];
            const float bg0 = bsum[512 + hj0], bg1 = bsum[512 + hj1];
            const float bo0 = bsum[768 + hj0], bo1 = bsum[768 + hj1];
            #pragma unroll
            for (int m = 0; m < 8; ++m) {
                const int mm = m0A + m;
                float2 vi = unpack2(acc[m * 4 + 0]);
                float2 vf = unpack2(acc[m * 4 + 1]);
                float2 vg = unpack2(acc[m * 4 + 2]);
                float2 vo = unpack2(acc[m * 4 + 3]);
                {
                    float iv = sig_f(vi.x + bi0), fv = sig_f(vf.x + bf0);
                    float gv = tanh_f(vg.x + bg0), ov = sig_f(vo.x + bo0);
                    float c = fv * c_reg[m * 2 + 0] + iv * gv;
                    c_reg[m * 2 + 0] = c;
                    hs[hj0 * MS + mm] = ov * tanh_f(c);
                }
                {
                    float iv = sig_f(vi.y + bi1), fv = sig_f(vf.y + bf1);
                    float gv = tanh_f(vg.y + bg1), ov = sig_f(vo.y + bo1);
                    float c = fv * c_reg[m * 2 + 1] + iv * gv;
                    c_reg[m * 2 + 1] = c;
                    hs[hj1 * MS + mm] = ov * tanh_f(c);
                }
            }
        }

        // ======== Phase 2a: [mu;logvar] = h @ [Wmu;Wvar]^T ========
        {
            issue2(0, 0); cpa_commit();
            issue2(1, 1); cpa_commit();
            issue2(2, 2); cpa_commit();

            ull acc2[4] = {0ULL, 0ULL, 0ULL, 0ULL};

            for (int p = 0; p < NP2; ++p) {
                cpa_wait2();
                __syncthreads();     // also orders phase-1 hs writes at p=0
                if (p + 3 < NP2) issue2(p + 3, (p + 3) & 3);
                cpa_commit();
                const float* wc = wbA + (p & 3) * SLOT2;
                const int k0 = p * PK2;
                #pragma unroll
                for (int kk = 0; kk < PK2; ++kk) {
                    float4 a = *(const float4*)(hs + (k0 + kk) * MS + m08);
                    ull w = *(const ull*)(wc + kk * 128 + jq2);
                    fma2(acc2[0], pack2s(a.x), w);
                    fma2(acc2[1], pack2s(a.y), w);
                    fma2(acc2[2], pack2s(a.z), w);
                    fma2(acc2[3], pack2s(a.w), w);
                }
            }
            __syncthreads();         // all warps done with panel slots

            // epilogue: row pair (jq2, jq2+1) for 4 m rows -> mus/lvs (slot0/1)
            if (jq2 < 64) {
                const float b0 = bmu_s[jq2], b1 = bmu_s[jq2 + 1];
                #pragma unroll
                for (int m = 0; m < 4; ++m) {
                    float2 v = unpack2(acc2[m]);
                    mus[jq2 * MS + m08 + m]       = v.x + b0;
                    mus[(jq2 + 1) * MS + m08 + m] = v.y + b1;
                }
            } else {
                const int l0 = jq2 - 64;
                const float b0 = bvar_s[l0], b1 = bvar_s[l0 + 1];
                #pragma unroll
                for (int m = 0; m < 4; ++m) {
                    float2 v = unpack2(acc2[m]);
                    lvs[l0 * MS + m08 + m]       = v.x + b0;
                    lvs[(l0 + 1) * MS + m08 + m] = v.y + b1;
                }
            }
        }
        __syncthreads();

        // ======== Phase 2b: gen/on + reparameterized z ========
        #pragma unroll
        for (int r = 0; r < 2; ++r) {
            const int m = wrp * 2 + r;
            const int b = bBase + m;
            float gp = 0.f, op = 0.f;
            #pragma unroll
            for (int i2 = 0; i2 < 8; ++i2) {
                int k = lane + 32 * i2;
                float hv = hs[k * MS + m];
                gp = fmaf(hv, wgv[k], gp);
                op = fmaf(hv, wov[k], op);
            }
            #pragma unroll
            for (int s2 = 16; s2 > 0; s2 >>= 1) {
                gp += __shfl_xor_sync(0xffffffffu, gp, s2);
                op += __shfl_xor_sync(0xffffffffu, op, s2);
            }
            if (lane == 0) {
                float gen = fmaxf(gp + bgv, 0.f);
                float on  = (op + bov) > 0.f ? 1.f : 0.f;
                abuf[m] = gen * on;
                out[O_GENS  + (size_t)b * T_STEPS + t] = gen;
                out[O_ONOFF + (size_t)b * T_STEPS + t] = on;
            }
            float mu0 = mus[lane * MS + m],        lv0 = lvs[lane * MS + m];
            float mu1 = mus[(lane + 32) * MS + m], lv1 = lvs[(lane + 32) * MS + m];
            zs[lane * MS + m]        = ea[r] * __expf(0.5f * lv0) + mu0;
            zs[(lane + 32) * MS + m] = eb[r] * __expf(0.5f * lv1) + mu1;
        }
        __syncwarp();

        // ======== Phase 3: delta = z@Wnext^T, state update, totals ========
        #pragma unroll
        for (int r = 0; r < 2; ++r) {
            const int m = wrp * 2 + r;
            const int b = bBase + m;
            float d0 = bnx_s[lane], d1 = bnx_s[lane + 32];
            #pragma unroll 8
            for (int l = 0; l < LAT; ++l) {
                float zl = zs[l * MS + m];
                d0 = fmaf(zl, wnT[l * 64 + lane],      d0);
                d1 = fmaf(zl, wnT[l * 64 + lane + 32], d1);
            }
            float xn0 = (lane == 0) ? 0.f : fmaxf(xs[lane * MS + m] + d0, 0.f);
            float xn1 = fmaxf(xs[(lane + 32) * MS + m] + d1, 0.f);
            float part = xn0 + xn1;
            #pragma unroll
            for (int s2 = 16; s2 > 0; s2 >>= 1)
                part += __shfl_xor_sync(0xffffffffu, part, s2);
            float add = abuf[m];
            float v0 = (lane == 0) ? add : xn0;
            size_t ob = O_STATES + ((size_t)b * T_STEPS + t) * D_IN;
            out[ob + lane]      = v0;
            out[ob + lane + 32] = xn1;
            xs[lane * MS + m]        = v0;
            xs[(lane + 32) * MS + m] = xn1;
            if (lane == 0) {
                out[O_TPRE  + (size_t)b * 128 + t + 1] = part;
                out[O_TPOST + (size_t)b * 128 + t + 1] = part + add;
            }
        }
        __syncthreads();   // xs/hs stable before next step's phase 1
    }
}

extern "C" void kernel_launch(void* const* d_in, const int* in_sizes, int n_in,
                              void* d_out, int out_size) {
    const float* data  = (const float*)d_in[0];
    const float* locs  = (const float*)d_in[1];
    const float* Wih   = (const float*)d_in[2];
    const float* Whh   = (const float*)d_in[3];
    const float* bih   = (const float*)d_in[4];
    const float* bhh   = (const float*)d_in[5];
    const float* Wmu   = (const float*)d_in[6];
    const float* bmu   = (const float*)d_in[7];
    const float* Wvar  = (const float*)d_in[8];
    const float* bvar  = (const float*)d_in[9];
    const float* Wvelo = (const float*)d_in[10];
    const float* bvelo = (const float*)d_in[11];
    const float* Wsw   = (const float*)d_in[12];
    const float* bsw   = (const float*)d_in[13];
    const float* Wgen  = (const float*)d_in[14];
    const float* bgen  = (const float*)d_in[15];
    const float* Won   = (const float*)d_in[16];
    const float* bon   = (const float*)d_in[17];
    const float* Wnext = (const float*)d_in[18];
    const float* bnext = (const float*)d_in[19];
    const float* Wloc  = (const float*)d_in[20];
    const float* bloc  = (const float*)d_in[21];
    const float* eps   = (const float*)d_in[22];
    float* out = (float*)d_out;

    prep_all_kernel<<<256, 512>>>(Wih, Whh, Wmu, Wvar,
                                  Wgen, bgen, Won, bon,
                                  Wvelo, bvelo, Wsw, bsw);

    // floats: 19680 (state) + 4 * 8192 (panel slots) = 52448
    const size_t smem_bytes = 52448 * sizeof(float);  // 209,792 B
    cudaFuncSetAttribute(model_kernel,
                         cudaFuncAttributeMaxDynamicSharedMemorySize,
                         (int)smem_bytes);
    model_kernel<<<NCTA, NTH, smem_bytes>>>(data, locs, bih, bhh,
                                            bmu, bvar, Wnext, bnext,
                                            Wloc, bloc, eps, out);
}

// round 12
// speedup vs baseline: 1.1150x; 1.0189x over previous
#include <cuda_runtime.h>

// Model_10582799417658: 127-step LSTM-VAE rollout.
// B=4096, D=64, H=256, GATES=1024, L=64, T=128 (127 scan steps).
//
// Round 12 (base = round-11 9503us): pair-granularity cp.async rings.
// Phase 1: 20 pair-iters (2 x 64KB slots), phase 2a: 4 pair-iters.
// Per-step __syncthreads 51 -> 27. Inner loops unchanged.

#define B_TOT   4096
#define T_STEPS 127
#define D_IN    64
#define HID     256
#define GATE    1024
#define LAT     64
#define BT      32
#define NTH     512
#define NCTA    (B_TOT / BT)   // 128
#define MS      36             // padded m-stride (floats)
#define NPP1    20             // phase-1 pairs (16 k each)
#define NPP2    4              // phase-2 pairs (64 k each)
#define SLOT1P  16384          // phase-1 pair-slot stride (floats, 64KB)
#define SLOT2P  8192           // phase-2 pair-slot stride (floats, 32KB)

// ---- output layout ----
#define N_STATES ((unsigned long long)B_TOT * T_STEPS * D_IN)
#define N_GENS   ((unsigned long long)B_TOT * T_STEPS)
#define N_TOTS   ((unsigned long long)B_TOT * 128)
#define O_STATES 0ULL
#define O_GENS   (O_STATES + N_STATES)
#define O_ONOFF  (O_GENS + N_GENS)
#define O_TPRE   (O_ONOFF + N_GENS)
#define O_TPOST  (O_TPRE + N_TOTS)

typedef unsigned long long ull;

__device__ float g_wgv[HID];
__device__ float g_wov[HID];
__device__ float g_b2[2];
// Phase-1 weights, k-major + gate-interleaved:
//   g_Wt1[k*1024 +       jp*4 + g*2 + jj] = Wg[(g  )*256 + jp*2 + jj][k], g in {0,1}
//   g_Wt1[k*1024 + 512 + jp*4 + g*2 + jj] = Wg[(g+2)*256 + jp*2 + jj][k], g in {0,1}
// where Wg row r: k<64 -> Wih[r][k], else Whh[r][k-64].
// Phase-2: g_Wt2[k][r] = (r<64 ? Wmu[r][k] : Wvar[r-64][k])
__device__ float g_Wt1[320 * 1024];
__device__ float g_Wt2[256 * 128];

__device__ __forceinline__ ull pack2s(float a) {   // splat (a, a)
    ull r;
    asm("mov.b64 %0, {%1,%1};" : "=l"(r) : "r"(__float_as_uint(a)));
    return r;
}
__device__ __forceinline__ void fma2(ull &d, ull a, ull b) {
    asm("fma.rn.f32x2 %0, %1, %2, %0;" : "+l"(d) : "l"(a), "l"(b));
}
__device__ __forceinline__ float2 unpack2(ull v) {
    unsigned int lo, hi;
    asm("mov.b64 {%0,%1}, %2;" : "=r"(lo), "=r"(hi) : "l"(v));
    float2 f; f.x = __uint_as_float(lo); f.y = __uint_as_float(hi);
    return f;
}
__device__ __forceinline__ float sig_f(float x) {
    return 1.0f / (1.0f + __expf(-x));
}
__device__ __forceinline__ float tanh_f(float x) {
    return 1.0f - 2.0f / (__expf(2.0f * x) + 1.0f);
}
__device__ __forceinline__ void cpa16(unsigned int dst, const void* src) {
    asm volatile("cp.async.cg.shared.global [%0], [%1], 16;" :: "r"(dst), "l"(src));
}
__device__ __forceinline__ void cpa_commit() {
    asm volatile("cp.async.commit_group;");
}
__device__ __forceinline__ void cpa_wait0() {
    asm volatile("cp.async.wait_group 0;");
}

// Merged one-time prep: rank-1 head folds + k-major weight transposes.
__global__ void prep_all_kernel(const float* __restrict__ Wih, const float* __restrict__ Whh,
                                const float* __restrict__ Wmu, const float* __restrict__ Wvar,
                                const float* __restrict__ Wgen, const float* __restrict__ bgen,
                                const float* __restrict__ Won,  const float* __restrict__ bon,
                                const float* __restrict__ Wvelo, const float* __restrict__ bvelo,
                                const float* __restrict__ Wsw,  const float* __restrict__ bsw) {
    const int stride = gridDim.x * blockDim.x;
    const int idx = blockIdx.x * blockDim.x + threadIdx.x;

    if (blockIdx.x == 0 && threadIdx.x < HID) {
        int k = threadIdx.x;
        float s1 = 0.f, s2 = 0.f;
        #pragma unroll 4
        for (int l = 0; l < LAT; ++l) {
            s1 += Wgen[l] * Wvelo[l * HID + k];
            s2 += Won[l]  * Wsw[l * HID + k];
        }
        g_wgv[k] = s1;
        g_wov[k] = s2;
        if (k == 0) {
            float b1 = bgen[0], b2 = bon[0];
            for (int l = 0; l < LAT; ++l) {
                b1 += Wgen[l] * bvelo[l];
                b2 += Won[l]  * bsw[l];
            }
            g_b2[0] = b1; g_b2[1] = b2;
        }
    }

    for (int i = idx; i < 320 * 1024; i += stride) {
        int k = i >> 10, d = i & 1023;
        int half = d >> 9, dd = d & 511;
        int jp = dd >> 2, q = dd & 3;
        int g = half * 2 + (q >> 1), jj = q & 1;
        int grow = g * 256 + jp * 2 + jj;
        g_Wt1[i] = (k < 64) ? Wih[grow * D_IN + k] : Whh[grow * HID + (k - 64)];
    }
    for (int i = idx; i < 256 * 128; i += stride) {
        int k = i >> 7, r = i & 127;
        g_Wt2[i] = (r < 64) ? Wmu[r * HID + k] : Wvar[(r - 64) * HID + k];
    }
}

__global__ void __launch_bounds__(NTH, 1)
model_kernel(const float* __restrict__ data, const float* __restrict__ locs,
             const float* __restrict__ bih,  const float* __restrict__ bhh,
             const float* __restrict__ bmu,  const float* __restrict__ bvar,
             const float* __restrict__ Wnext, const float* __restrict__ bnext,
             const float* __restrict__ Wloc, const float* __restrict__ bloc,
             const float* __restrict__ eps,  float* __restrict__ out) {
    extern __shared__ float sm[];
    float* xs     = sm;                  // [64][MS]
    float* hs     = xs     + 2304;       // [256][MS]  in-place h
    float* zs     = hs     + 9216;       // [64][MS]
    float* bsum   = zs     + 2304;       // [1024]
    float* wgv    = bsum   + 1024;       // [256]
    float* wov    = wgv    + 256;        // [256]
    float* bmu_s  = wov    + 256;        // [64]
    float* bvar_s = bmu_s  + 64;         // [64]
    float* bnx_s  = bvar_s + 64;         // [64]
    float* wnT    = bnx_s  + 64;         // [64][64]
    float* abuf   = wnT    + 4096;       // [32]
    float* wbA    = abuf   + 32;         // panel area: 2 x SLOT1P (32768 floats)
    float* mus    = wbA;                 // [64][MS]  (reuse after phase 2a)
    float* lvs    = wbA + 2304;          // [64][MS]

    const unsigned int wb_u32 =
        (unsigned int)__cvta_generic_to_shared(wbA);

    const int tid   = threadIdx.x;
    const int bBase = blockIdx.x * BT;
    // phase-1 tile: 4 m-tiles of 8 rows x 128 j-pairs (x4 gates)
    const int m0A  = (tid & 3) * 8;
    const int jp   = tid >> 2;           // 0..127
    const int jt2A = jp * 2;
    const int wrp = tid >> 5, lane = tid & 31;
    // phase-2a tile: 8 m-tiles of 4 x 64 row-pairs
    const int m08 = (tid & 7) * 4;
    const int jq2 = (tid >> 3) * 2;      // 0..126

    // ---------------- init ----------------
    for (int i = tid; i < D_IN * BT; i += NTH) {
        int k = i / BT, m = i % BT;
        xs[k * MS + m] = data[(size_t)(bBase + m) * (128 * D_IN) + k];
    }
    for (int i = tid; i < HID * BT; i += NTH) {
        int j = i / BT, m = i % BT;
        int b = bBase + m;
        hs[j * MS + m] = locs[b * 2] * Wloc[j * 2] + locs[b * 2 + 1] * Wloc[j * 2 + 1] + bloc[j];
    }
    for (int i = tid; i < GATE; i += NTH) bsum[i] = bih[i] + bhh[i];
    for (int i = tid; i < HID; i += NTH) { wgv[i] = g_wgv[i]; wov[i] = g_wov[i]; }
    for (int i = tid; i < LAT; i += NTH) { bmu_s[i] = bmu[i]; bvar_s[i] = bvar[i]; }
    for (int i = tid; i < D_IN; i += NTH) bnx_s[i] = bnext[i];
    for (int i = tid; i < LAT * D_IN; i += NTH) {   // wnT[l][c] = Wnext[c][l]
        int l = i >> 6, c = i & 63;
        wnT[i] = Wnext[c * LAT + l];
    }
    if (tid < BT) {
        out[O_TPRE  + (size_t)(bBase + tid) * 128] = 0.f;
        out[O_TPOST + (size_t)(bBase + tid) * 128] = 0.f;
    }
    const float bgv = g_b2[0], bov = g_b2[1];

    // c state in registers: this thread owns cols (jt2A, jt2A+1) x rows m0A..m0A+7
    float c_reg[16];
    #pragma unroll
    for (int i = 0; i < 16; ++i) c_reg[i] = 0.f;
    __syncthreads();

    // pair issue helpers (cp.async, 16B granules)
    auto issue1 = [&](int pp, int slot) {   // 16384 floats = 8 x 512 float4
        const float4* src = ((const float4*)g_Wt1) + (size_t)pp * 4096 + tid;
        unsigned int dst = wb_u32 + (unsigned int)slot * (SLOT1P * 4u) + tid * 16u;
        #pragma unroll
        for (int i = 0; i < 8; ++i)
            cpa16(dst + (unsigned int)i * 8192u, src + i * 512);
    };
    auto issue2 = [&](int pp, int slot) {   // 8192 floats = 4 x 512 float4
        const float4* src = ((const float4*)g_Wt2) + (size_t)pp * 2048 + tid;
        unsigned int dst = wb_u32 + (unsigned int)slot * (SLOT2P * 4u) + tid * 16u;
        #pragma unroll
        for (int i = 0; i < 4; ++i)
            cpa16(dst + (unsigned int)i * 8192u, src + i * 512);
    };

    for (int t = 0; t < T_STEPS; ++t) {
        // prefetch eps for phase 2b
        float ea[2], eb[2];
        {
            const int mr = wrp * 2;
            const float* ep = eps + ((size_t)t * B_TOT + bBase + mr) * LAT;
            ea[0] = __ldg(ep + lane);        eb[0] = __ldg(ep + lane + 32);
            ea[1] = __ldg(ep + LAT + lane);  eb[1] = __ldg(ep + LAT + lane + 32);
        }

        // ======== Phase 1: gates = x@Wih^T + h@Whh^T, LSTM update ========
        {
            issue1(0, 0); cpa_commit();

            ull acc[32];
            #pragma unroll
            for (int i = 0; i < 32; ++i) acc[i] = 0ULL;

            for (int pp = 0; pp < NPP1; ++pp) {
                cpa_wait0();         // pair pp arrived (this thread's copies)
                __syncthreads();     // visible to all; pair pp-1 fully consumed
                if (pp + 1 < NPP1) { issue1(pp + 1, (pp + 1) & 1); cpa_commit(); }
                const float* wc = wbA + (pp & 1) * SLOT1P;
                const float* Ab = (pp < 4) ? (xs + pp * 16 * MS)
                                           : (hs + (pp * 16 - 64) * MS);
                #pragma unroll
                for (int kk = 0; kk < 16; ++kk) {
                    float4 a0 = *(const float4*)(Ab + kk * MS + m0A);
                    float4 a1 = *(const float4*)(Ab + kk * MS + m0A + 4);
                    const float* wr = wc + kk * 1024 + jp * 4;
                    ulonglong2 wA = *(const ulonglong2*)(wr);        // g0, g1
                    ulonglong2 wB = *(const ulonglong2*)(wr + 512);  // g2, g3
                    ull w0 = wA.x, w1 = wA.y, w2 = wB.x, w3 = wB.y;
                    #pragma unroll
                    for (int m = 0; m < 4; ++m) {
                        ull am = pack2s((&a0.x)[m]);
                        fma2(acc[m * 4 + 0], am, w0);
                        fma2(acc[m * 4 + 1], am, w1);
                        fma2(acc[m * 4 + 2], am, w2);
                        fma2(acc[m * 4 + 3], am, w3);
                    }
                    #pragma unroll
                    for (int m = 0; m < 4; ++m) {
                        ull am = pack2s((&a1.x)[m]);
                        fma2(acc[(m + 4) * 4 + 0], am, w0);
                        fma2(acc[(m + 4) * 4 + 1], am, w1);
                        fma2(acc[(m + 4) * 4 + 2], am, w2);
                        fma2(acc[(m + 4) * 4 + 3], am, w3);
                    }
                }
            }
            __syncthreads();         // all warps done reading hs/panels

            // epilogue: bias + LSTM nonlinearity; c in regs, h in place
            const int hj0 = jt2A, hj1 = jt2A + 1;
            const float bi0 = bsum[hj0],       bi1 = bsum[hj1];
            const float bf0 = bsum[256 + hj0], bf1 = bsum[256 + hj1];
            const float bg0 = bsum[512 + hj0], bg1 = bsum[512 + hj1];
            const float bo0 = bsum[768 + hj0], bo1 = bsum[768 + hj1];
            #pragma unroll
            for (int m = 0; m < 8; ++m) {
                const int mm = m0A + m;
                float2 vi = unpack2(acc[m * 4 + 0]);
                float2 vf = unpack2(acc[m * 4 + 1]);
                float2 vg = unpack2(acc[m * 4 + 2]);
                float2 vo = unpack2(acc[m * 4 + 3]);
                {
                    float iv = sig_f(vi.x + bi0), fv = sig_f(vf.x + bf0);
                    float gv = tanh_f(vg.x + bg0), ov = sig_f(vo.x + bo0);
                    float c = fv * c_reg[m * 2 + 0] + iv * gv;
                    c_reg[m * 2 + 0] = c;
                    hs[hj0 * MS + mm] = ov * tanh_f(c);
                }
                {
                    float iv = sig_f(vi.y + bi1), fv = sig_f(vf.y + bf1);
                    float gv = tanh_f(vg.y + bg1), ov = sig_f(vo.y + bo1);
                    float c = fv * c_reg[m * 2 + 1] + iv * gv;
                    c_reg[m * 2 + 1] = c;
                    hs[hj1 * MS + mm] = ov * tanh_f(c);
                }
            }
        }

        // ======== Phase 2a: [mu;logvar] = h @ [Wmu;Wvar]^T ========
        {
            issue2(0, 0); cpa_commit();

            ull acc2[4] = {0ULL, 0ULL, 0ULL, 0ULL};

            for (int pp = 0; pp < NPP2; ++pp) {
                cpa_wait0();
                __syncthreads();     // also orders phase-1 hs epilogue writes
                if (pp + 1 < NPP2) { issue2(pp + 1, (pp + 1) & 1); cpa_commit(); }
                const float* wc = wbA + (pp & 1) * SLOT2P;
                const int k0 = pp * 64;
                #pragma unroll 16
                for (int kk = 0; kk < 64; ++kk) {
                    float4 a = *(const float4*)(hs + (k0 + kk) * MS + m08);
                    ull w = *(const ull*)(wc + kk * 128 + jq2);
                    fma2(acc2[0], pack2s(a.x), w);
                    fma2(acc2[1], pack2s(a.y), w);
                    fma2(acc2[2], pack2s(a.z), w);
                    fma2(acc2[3], pack2s(a.w), w);
                }
            }
            __syncthreads();         // all warps done with panel slots

            // epilogue: row pair (jq2, jq2+1) for 4 m rows -> mus/lvs (slot0)
            if (jq2 < 64) {
                const float b0 = bmu_s[jq2], b1 = bmu_s[jq2 + 1];
                #pragma unroll
                for (int m = 0; m < 4; ++m) {
                    float2 v = unpack2(acc2[m]);
                    mus[jq2 * MS + m08 + m]       = v.x + b0;
                    mus[(jq2 + 1) * MS + m08 + m] = v.y + b1;
                }
            } else {
                const int l0 = jq2 - 64;
                const float b0 = bvar_s[l0], b1 = bvar_s[l0 + 1];
                #pragma unroll
                for (int m = 0; m < 4; ++m) {
                    float2 v = unpack2(acc2[m]);
                    lvs[l0 * MS + m08 + m]       = v.x + b0;
                    lvs[(l0 + 1) * MS + m08 + m] = v.y + b1;
                }
            }
        }
        __syncthreads();

        // ======== Phase 2b: gen/on + reparameterized z ========
        #pragma unroll
        for (int r = 0; r < 2; ++r) {
            const int m = wrp * 2 + r;
            const int b = bBase + m;
            float gp = 0.f, op = 0.f;
            #pragma unroll
            for (int i2 = 0; i2 < 8; ++i2) {
                int k = lane + 32 * i2;
                float hv = hs[k * MS + m];
                gp = fmaf(hv, wgv[k], gp);
                op = fmaf(hv, wov[k], op);
            }
            #pragma unroll
            for (int s2 = 16; s2 > 0; s2 >>= 1) {
                gp += __shfl_xor_sync(0xffffffffu, gp, s2);
                op += __shfl_xor_sync(0xffffffffu, op, s2);
            }
            if (lane == 0) {
                float gen = fmaxf(gp + bgv, 0.f);
                float on  = (op + bov) > 0.f ? 1.f : 0.f;
                abuf[m] = gen * on;
                out[O_GENS  + (size_t)b * T_STEPS + t] = gen;
                out[O_ONOFF + (size_t)b * T_STEPS + t] = on;
            }
            float mu0 = mus[lane * MS + m],        lv0 = lvs[lane * MS + m];
            float mu1 = mus[(lane + 32) * MS + m], lv1 = lvs[(lane + 32) * MS + m];
            zs[lane * MS + m]        = ea[r] * __expf(0.5f * lv0) + mu0;
            zs[(lane + 32) * MS + m] = eb[r] * __expf(0.5f * lv1) + mu1;
        }
        __syncwarp();

        // ======== Phase 3: delta = z@Wnext^T, state update, totals ========
        #pragma unroll
        for (int r = 0; r < 2; ++r) {
            const int m = wrp * 2 + r;
            const int b = bBase + m;
            float d0 = bnx_s[lane], d1 = bnx_s[lane + 32];
            #pragma unroll 8
            for (int l = 0; l < LAT; ++l) {
                float zl = zs[l * MS + m];
                d0 = fmaf(zl, wnT[l * 64 + lane],      d0);
                d1 = fmaf(zl, wnT[l * 64 + lane + 32], d1);
            }
            float xn0 = (lane == 0) ? 0.f : fmaxf(xs[lane * MS + m] + d0, 0.f);
            float xn1 = fmaxf(xs[(lane + 32) * MS + m] + d1, 0.f);
            float part = xn0 + xn1;
            #pragma unroll
            for (int s2 = 16; s2 > 0; s2 >>= 1)
                part += __shfl_xor_sync(0xffffffffu, part, s2);
            float add = abuf[m];
            float v0 = (lane == 0) ? add : xn0;
            size_t ob = O_STATES + ((size_t)b * T_STEPS + t) * D_IN;
            out[ob + lane]      = v0;
            out[ob + lane + 32] = xn1;
            xs[lane * MS + m]        = v0;
            xs[(lane + 32) * MS + m] = xn1;
            if (lane == 0) {
                out[O_TPRE  + (size_t)b * 128 + t + 1] = part;
                out[O_TPOST + (size_t)b * 128 + t + 1] = part + add;
            }
        }
        __syncthreads();   // xs/hs stable before next step's phase 1
    }
}

extern "C" void kernel_launch(void* const* d_in, const int* in_sizes, int n_in,
                              void* d_out, int out_size) {
    const float* data  = (const float*)d_in[0];
    const float* locs  = (const float*)d_in[1];
    const float* Wih   = (const float*)d_in[2];
    const float* Whh   = (const float*)d_in[3];
    const float* bih   = (const float*)d_in[4];
    const float* bhh   = (const float*)d_in[5];
    const float* Wmu   = (const float*)d_in[6];
    const float* bmu   = (const float*)d_in[7];
    const float* Wvar  = (const float*)d_in[8];
    const float* bvar  = (const float*)d_in[9];
    const float* Wvelo = (const float*)d_in[10];
    const float* bvelo = (const float*)d_in[11];
    const float* Wsw   = (const float*)d_in[12];
    const float* bsw   = (const float*)d_in[13];
    const float* Wgen  = (const float*)d_in[14];
    const float* bgen  = (const float*)d_in[15];
    const float* Won   = (const float*)d_in[16];
    const float* bon   = (const float*)d_in[17];
    const float* Wnext = (const float*)d_in[18];
    const float* bnext = (const float*)d_in[19];
    const float* Wloc  = (const float*)d_in[20];
    const float* bloc  = (const float*)d_in[21];
    const float* eps   = (const float*)d_in[22];
    float* out = (float*)d_out;

    prep_all_kernel<<<256, 512>>>(Wih, Whh, Wmu, Wvar,
                                  Wgen, bgen, Won, bon,
                                  Wvelo, bvelo, Wsw, bsw);

    // floats: 19680 (state) + 2 * 16384 (pair slots) = 52448
    const size_t smem_bytes = 52448 * sizeof(float);  // 209,792 B
    cudaFuncSetAttribute(model_kernel,
                         cudaFuncAttributeMaxDynamicSharedMemorySize,
                         (int)smem_bytes);
    model_kernel<<<NCTA, NTH, smem_bytes>>>(data, locs, bih, bhh,
                                            bmu, bvar, Wnext, bnext,
                                            Wloc, bloc, eps, out);
}